// round 6
// baseline (speedup 1.0000x reference)
#include <cuda_runtime.h>
#include <cuda_bf16.h>
#include <cstdint>

// ============================================================================
// out = alpha*x + U * diag(g(lam)) * U^T * x       (Lambda diagonal)
// g(l) = sum_i 4*c_i/(a_i-b_i)^2 * relu((a_i-l)(l-b_i))
//
// Engine: mma.sync m16n8k16 bf16 (fp32 accum), hi/lo compensation
// (D += Ah*Bh + Ah*Bl + Al*Bh).  R6: 3-stage cp.async ring + fragment
// double-buffering (LDSM of ks+1 overlapped with MMAs of ks), single
// __syncthreads per k-tile.
// ============================================================================

#define NDIM 2048
#define FDIM 256
#define KDIM 2048
#define BT   64            // CTA tile (M and N)
#define KT   64            // k-tile (64 bf16 = 128B row, SW128 swizzle)
#define NKT  (KDIM / KT)   // 32
#define NSTG 3

#define STAGE_BYTES 32768  // Ah 8K | Al 8K | Bh 8K | Bl 8K
#define SMEM_DYN    (1024 + NSTG * STAGE_BYTES)

// ------------------------- device scratch (no cudaMalloc) -------------------
__device__ __align__(16) __nv_bfloat16 g_Uhi [NDIM * NDIM];
__device__ __align__(16) __nv_bfloat16 g_Ulo [NDIM * NDIM];
__device__ __align__(16) __nv_bfloat16 g_Uthi[NDIM * NDIM];
__device__ __align__(16) __nv_bfloat16 g_Utlo[NDIM * NDIM];
__device__ __align__(16) __nv_bfloat16 g_Xthi[FDIM * NDIM];
__device__ __align__(16) __nv_bfloat16 g_Xtlo[FDIM * NDIM];
__device__ __align__(16) __nv_bfloat16 g_Wthi[FDIM * NDIM];
__device__ __align__(16) __nv_bfloat16 g_Wtlo[FDIM * NDIM];
__device__ float g_g[NDIM];

// ------------------------------- helpers ------------------------------------
__device__ __forceinline__ unsigned s2u(const void* p) {
    unsigned a;
    asm("{ .reg .u64 t; cvta.to.shared.u64 t, %1; cvt.u32.u64 %0, t; }" : "=r"(a) : "l"(p));
    return a;
}
__device__ __forceinline__ unsigned swz(unsigned o) { return o ^ ((o >> 3) & 0x70); }

__device__ __forceinline__ void cpa16(unsigned s, const void* g) {
    asm volatile("cp.async.cg.shared.global [%0], [%1], 16;" :: "r"(s), "l"(g));
}
__device__ __forceinline__ void ldm_x4(unsigned* r, unsigned addr) {
    asm volatile("ldmatrix.sync.aligned.m8n8.x4.shared.b16 {%0,%1,%2,%3}, [%4];"
                 : "=r"(r[0]), "=r"(r[1]), "=r"(r[2]), "=r"(r[3]) : "r"(addr));
}
__device__ __forceinline__ void mma16816(float* d, const unsigned* a, const unsigned* b) {
    asm volatile("mma.sync.aligned.m16n8k16.row.col.f32.bf16.bf16.f32 "
                 "{%0,%1,%2,%3}, {%4,%5,%6,%7}, {%8,%9}, {%0,%1,%2,%3};"
                 : "+f"(d[0]), "+f"(d[1]), "+f"(d[2]), "+f"(d[3])
                 : "r"(a[0]), "r"(a[1]), "r"(a[2]), "r"(a[3]), "r"(b[0]), "r"(b[1]));
}

// ------------------------------ prep kernels --------------------------------
__global__ void prep_g_k(const float* __restrict__ lam, const float* __restrict__ a,
                         const float* __restrict__ b, const float* __restrict__ c, int nf) {
    int j = blockIdx.x * blockDim.x + threadIdx.x;
    if (j >= NDIM) return;
    float lv = lam[(size_t)j * NDIM + j];
    float g = 0.f;
    for (int i = 0; i < nf; ++i) {
        float at = a[i], bt = b[i];
        float d = (at - lv) * (lv - bt);
        d = d > 0.f ? d : 0.f;
        float ab = at - bt;
        g += (4.f * c[i] / (ab * ab)) * d;
    }
    g_g[j] = g;
}

__global__ void prep_U_k(const float* __restrict__ U) {
    __shared__ float t[32][33];
    const int bx = blockIdx.x * 32, by = blockIdx.y * 32;
    const int tx = threadIdx.x, ty = threadIdx.y;
#pragma unroll
    for (int i = 0; i < 4; ++i) {
        int r = ty + i * 8;
        float v = U[(size_t)(by + r) * NDIM + bx + tx];
        t[r][tx] = v;
        __nv_bfloat16 h = __float2bfloat16(v);
        size_t o = (size_t)(by + r) * NDIM + bx + tx;
        g_Uhi[o] = h;
        g_Ulo[o] = __float2bfloat16(v - __bfloat162float(h));
    }
    __syncthreads();
#pragma unroll
    for (int i = 0; i < 4; ++i) {
        int r = ty + i * 8;
        float v = t[tx][r];                            // U[by+tx, bx+r]
        __nv_bfloat16 h = __float2bfloat16(v);
        size_t o = (size_t)(bx + r) * NDIM + by + tx;  // Ut[bx+r, by+tx]
        g_Uthi[o] = h;
        g_Utlo[o] = __float2bfloat16(v - __bfloat162float(h));
    }
}

__global__ void prep_X_k(const float* __restrict__ X) {
    __shared__ float t[32][33];
    const int bx = blockIdx.x * 32, by = blockIdx.y * 32;   // bx over F, by over N
    const int tx = threadIdx.x, ty = threadIdx.y;
#pragma unroll
    for (int i = 0; i < 4; ++i) {
        int r = ty + i * 8;
        t[r][tx] = X[(size_t)(by + r) * FDIM + bx + tx];
    }
    __syncthreads();
#pragma unroll
    for (int i = 0; i < 4; ++i) {
        int r = ty + i * 8;
        float v = t[tx][r];                            // X[by+tx, bx+r]
        __nv_bfloat16 h = __float2bfloat16(v);
        size_t o = (size_t)(bx + r) * NDIM + by + tx;  // Xt[bx+r, by+tx]
        g_Xthi[o] = h;
        g_Xtlo[o] = __float2bfloat16(v - __bfloat162float(h));
    }
}

// --------------------------- mma.sync GEMM kernel ---------------------------
struct Frag { unsigned ah[4], al[4], bh[2][4], bl[2][4]; };

__global__ __launch_bounds__(256)
void gemm_mma(int mode, const float* __restrict__ X,
              const float* __restrict__ alpha, float* __restrict__ out)
{
    extern __shared__ char smem_raw[];
    const unsigned sb = (s2u(smem_raw) + 1023u) & ~1023u;

    const int tid = threadIdx.x;
    const int wid = tid >> 5, lane = tid & 31;
    const int warp_m = wid >> 1, warp_n = wid & 1;   // 4 x 2 warps, 16x32 tiles
    const int m0 = blockIdx.x * BT, n0 = blockIdx.y * BT;

    const __nv_bfloat16 *Ah, *Al, *Bh, *Bl;
    if (mode == 0) { Ah = g_Xthi; Al = g_Xtlo; Bh = g_Uthi; Bl = g_Utlo; }
    else           { Ah = g_Uhi;  Al = g_Ulo;  Bh = g_Wthi; Bl = g_Wtlo; }

    // -------- load plan: 8 cp.async x 16B per thread per stage --------
    const __nv_bfloat16* srcs[4] = {
        Ah + (size_t)m0 * KDIM, Al + (size_t)m0 * KDIM,
        Bh + (size_t)n0 * KDIM, Bl + (size_t)n0 * KDIM };
    unsigned soff[8], goff[8];
#pragma unroll
    for (int i = 0; i < 8; ++i) {
        int arr = i >> 1;
        int l = (i & 1) * 256 + tid;       // 0..511
        int row = l >> 3, c = l & 7;
        soff[i] = arr * 8192 + swz(row * 128 + c * 16);
        goff[i] = row * KDIM + c * 8;
    }
    auto load_tile = [&](int t, int stage) {
        const unsigned st = sb + stage * STAGE_BYTES;
        const unsigned kb = t * KT;
#pragma unroll
        for (int i = 0; i < 8; ++i)
            cpa16(st + soff[i], srcs[i >> 1] + goff[i] + kb);
        asm volatile("cp.async.commit_group;" ::: "memory");
    };

    // -------- ldmatrix address bases --------
    const unsigned abase =
        (warp_m * 16 + ((lane >> 3) & 1) * 8 + (lane & 7)) * 128 + (lane >> 4) * 16;
    unsigned bbase[2];
#pragma unroll
    for (int nf2 = 0; nf2 < 2; ++nf2) {
        int rowB = warp_n * 32 + nf2 * 16 + ((lane >> 4) & 1) * 8 + (lane & 7);
        bbase[nf2] = rowB * 128 + ((lane >> 3) & 1) * 16;
    }

    auto frag_ld = [&](unsigned stA, int ks, Frag& f) {
        const unsigned stB = stA + 16384;
        ldm_x4(f.ah, stA + swz(abase + ks * 32));
        ldm_x4(f.al, stA + 8192 + swz(abase + ks * 32));
#pragma unroll
        for (int nf2 = 0; nf2 < 2; ++nf2) {
            ldm_x4(f.bh[nf2], stB + swz(bbase[nf2] + ks * 32));
            ldm_x4(f.bl[nf2], stB + 8192 + swz(bbase[nf2] + ks * 32));
        }
    };

    float acc[4][4] = {};
    Frag fr[2];

    // prologue: 2 tiles in flight, frags for (t=0, ks=0) resident
    load_tile(0, 0);
    load_tile(1, 1);
    asm volatile("cp.async.wait_group 1;" ::: "memory");
    __syncthreads();
    frag_ld(sb, 0, fr[0]);

    int scur = 0;
#pragma unroll 1
    for (int t = 0; t < NKT; ++t) {
        const unsigned stA = sb + scur * STAGE_BYTES;
        int s2 = scur + 2; if (s2 >= NSTG) s2 -= NSTG;
        if (t + 2 < NKT) load_tile(t + 2, s2);

#pragma unroll
        for (int ks = 0; ks < 4; ++ks) {
            Frag& cur = fr[ks & 1];
            if (ks < 3) frag_ld(stA, ks + 1, fr[(ks & 1) ^ 1]);
#pragma unroll
            for (int nf = 0; nf < 4; ++nf) {
                const unsigned* bhp = &cur.bh[nf >> 1][(nf & 1) * 2];
                const unsigned* blp = &cur.bl[nf >> 1][(nf & 1) * 2];
                mma16816(acc[nf], cur.ah, bhp);
                mma16816(acc[nf], cur.ah, blp);
                mma16816(acc[nf], cur.al, bhp);
            }
        }

        if (t + 1 < NKT) {
            if (t + 2 < NKT) asm volatile("cp.async.wait_group 1;" ::: "memory");
            else             asm volatile("cp.async.wait_group 0;" ::: "memory");
            __syncthreads();
            int s1 = scur + 1; if (s1 >= NSTG) s1 -= NSTG;
            frag_ld(sb + s1 * STAGE_BYTES, 0, fr[0]);
        }
        scur = scur + 1; if (scur >= NSTG) scur -= NSTG;
    }

    // ------------------------------ epilogue --------------------------------
    const int rbase = m0 + warp_m * 16 + (lane >> 2);
    const int cbase0 = n0 + warp_n * 32 + (lane & 3) * 2;

    if (mode == 0) {
#pragma unroll
        for (int nf = 0; nf < 4; ++nf) {
            const int cb = cbase0 + nf * 8;
            const float g0 = g_g[cb], g1 = g_g[cb + 1];
#pragma unroll
            for (int h = 0; h < 2; ++h) {
                const int row = rbase + h * 8;
                float v0 = acc[nf][h * 2 + 0] * g0;
                float v1 = acc[nf][h * 2 + 1] * g1;
                __nv_bfloat16 h0 = __float2bfloat16(v0);
                __nv_bfloat16 h1 = __float2bfloat16(v1);
                __nv_bfloat162 hv; hv.x = h0; hv.y = h1;
                __nv_bfloat162 lv;
                lv.x = __float2bfloat16(v0 - __bfloat162float(h0));
                lv.y = __float2bfloat16(v1 - __bfloat162float(h1));
                *(__nv_bfloat162*)(g_Wthi + (size_t)row * NDIM + cb) = hv;
                *(__nv_bfloat162*)(g_Wtlo + (size_t)row * NDIM + cb) = lv;
            }
        }
    } else {
        const float av = alpha[0];
#pragma unroll
        for (int nf = 0; nf < 4; ++nf) {
            const int cb = cbase0 + nf * 8;
#pragma unroll
            for (int h = 0; h < 2; ++h) {
                const int row = rbase + h * 8;
                const float2 xv = *(const float2*)(X + (size_t)row * FDIM + cb);
                float2 o;
                o.x = av * xv.x + acc[nf][h * 2 + 0];
                o.y = av * xv.y + acc[nf][h * 2 + 1];
                *(float2*)(out + (size_t)row * FDIM + cb) = o;
            }
        }
    }
}

// ---------------------------------------------------------------------------
extern "C" void kernel_launch(void* const* d_in, const int* in_sizes, int n_in,
                              void* d_out, int out_size)
{
    const float* X     = (const float*)d_in[0];  // [N,F]
    const float* Lam   = (const float*)d_in[1];  // [N,N] diagonal
    const float* U     = (const float*)d_in[2];  // [N,N]
    const float* a     = (const float*)d_in[3];
    const float* b     = (const float*)d_in[4];
    const float* c     = (const float*)d_in[5];
    const float* alpha = (const float*)d_in[6];
    // d_in[7] = edge_index (unused by the reference math)
    const int nf = in_sizes[3];

    static bool attr_set = false;
    if (!attr_set) {
        cudaFuncSetAttribute(gemm_mma, cudaFuncAttributeMaxDynamicSharedMemorySize, SMEM_DYN);
        attr_set = true;
    }

    prep_g_k<<<NDIM / 256, 256>>>(Lam, a, b, c, nf);
    dim3 bt(32, 8);
    prep_X_k<<<dim3(FDIM / 32, NDIM / 32), bt>>>(X);
    prep_U_k<<<dim3(NDIM / 32, NDIM / 32), bt>>>(U);

    // GEMM1: M=FDIM(256) x N=NDIM(2048):  grid 4 x 32
    gemm_mma<<<dim3(FDIM / BT, NDIM / BT), 256, SMEM_DYN>>>(0, X, alpha, (float*)d_out);
    // GEMM2: M=NDIM(2048) x N=FDIM(256):  grid 32 x 4
    gemm_mma<<<dim3(NDIM / BT, FDIM / BT), 256, SMEM_DYN>>>(1, X, alpha, (float*)d_out);
}

// round 7
// speedup vs baseline: 1.1192x; 1.1192x over previous
#include <cuda_runtime.h>
#include <cuda_bf16.h>
#include <cstdint>

// ============================================================================
// out = alpha*x + U * diag(g(lam)) * U^T * x       (Lambda diagonal)
// g(l) = sum_i 4*c_i/(a_i-b_i)^2 * relu((a_i-l)(l-b_i))
//
// Engine: mma.sync m16n8k16 bf16 (fp32 accum), hi/lo compensation.
// R7: split accumulators (accH for Ah*Bh, accX for the two cross terms) so
// the 3 compensation MMAs per (nf,ks) no longer form a 3-deep RAW chain.
// Structure otherwise identical to the 62us R5 kernel (2-stage cp.async ring).
// ============================================================================

#define NDIM 2048
#define FDIM 256
#define KDIM 2048
#define BT   64            // CTA tile (M and N)
#define KT   64            // k-tile (64 bf16 = 128B row -> SW128 atoms)
#define NKT  (KDIM / KT)   // 32

#define STAGE_BYTES 32768  // Ah 8K | Al 8K | Bh 8K | Bl 8K
#define SMEM_DYN    (1024 + 2 * STAGE_BYTES)

// ------------------------- device scratch (no cudaMalloc) -------------------
__device__ __align__(16) __nv_bfloat16 g_Uhi [NDIM * NDIM];
__device__ __align__(16) __nv_bfloat16 g_Ulo [NDIM * NDIM];
__device__ __align__(16) __nv_bfloat16 g_Uthi[NDIM * NDIM];
__device__ __align__(16) __nv_bfloat16 g_Utlo[NDIM * NDIM];
__device__ __align__(16) __nv_bfloat16 g_Xthi[FDIM * NDIM];
__device__ __align__(16) __nv_bfloat16 g_Xtlo[FDIM * NDIM];
__device__ __align__(16) __nv_bfloat16 g_Wthi[FDIM * NDIM];
__device__ __align__(16) __nv_bfloat16 g_Wtlo[FDIM * NDIM];
__device__ float g_g[NDIM];

// ------------------------------- helpers ------------------------------------
__device__ __forceinline__ unsigned s2u(const void* p) {
    unsigned a;
    asm("{ .reg .u64 t; cvta.to.shared.u64 t, %1; cvt.u32.u64 %0, t; }" : "=r"(a) : "l"(p));
    return a;
}
__device__ __forceinline__ unsigned swz(unsigned o) { return o ^ ((o >> 3) & 0x70); }

__device__ __forceinline__ void cpa16(unsigned s, const void* g) {
    asm volatile("cp.async.cg.shared.global [%0], [%1], 16;" :: "r"(s), "l"(g));
}
__device__ __forceinline__ void ldm_x4(unsigned* r, unsigned addr) {
    asm volatile("ldmatrix.sync.aligned.m8n8.x4.shared.b16 {%0,%1,%2,%3}, [%4];"
                 : "=r"(r[0]), "=r"(r[1]), "=r"(r[2]), "=r"(r[3]) : "r"(addr));
}
__device__ __forceinline__ void mma16816(float* d, const unsigned* a, const unsigned* b) {
    asm volatile("mma.sync.aligned.m16n8k16.row.col.f32.bf16.bf16.f32 "
                 "{%0,%1,%2,%3}, {%4,%5,%6,%7}, {%8,%9}, {%0,%1,%2,%3};"
                 : "+f"(d[0]), "+f"(d[1]), "+f"(d[2]), "+f"(d[3])
                 : "r"(a[0]), "r"(a[1]), "r"(a[2]), "r"(a[3]), "r"(b[0]), "r"(b[1]));
}

// ------------------------------ prep kernels --------------------------------
__global__ void prep_g_k(const float* __restrict__ lam, const float* __restrict__ a,
                         const float* __restrict__ b, const float* __restrict__ c, int nf) {
    int j = blockIdx.x * blockDim.x + threadIdx.x;
    if (j >= NDIM) return;
    float lv = lam[(size_t)j * NDIM + j];
    float g = 0.f;
    for (int i = 0; i < nf; ++i) {
        float at = a[i], bt = b[i];
        float d = (at - lv) * (lv - bt);
        d = d > 0.f ? d : 0.f;
        float ab = at - bt;
        g += (4.f * c[i] / (ab * ab)) * d;
    }
    g_g[j] = g;
}

__global__ void prep_U_k(const float* __restrict__ U) {
    __shared__ float t[32][33];
    const int bx = blockIdx.x * 32, by = blockIdx.y * 32;
    const int tx = threadIdx.x, ty = threadIdx.y;
#pragma unroll
    for (int i = 0; i < 4; ++i) {
        int r = ty + i * 8;
        float v = U[(size_t)(by + r) * NDIM + bx + tx];
        t[r][tx] = v;
        __nv_bfloat16 h = __float2bfloat16(v);
        size_t o = (size_t)(by + r) * NDIM + bx + tx;
        g_Uhi[o] = h;
        g_Ulo[o] = __float2bfloat16(v - __bfloat162float(h));
    }
    __syncthreads();
#pragma unroll
    for (int i = 0; i < 4; ++i) {
        int r = ty + i * 8;
        float v = t[tx][r];                            // U[by+tx, bx+r]
        __nv_bfloat16 h = __float2bfloat16(v);
        size_t o = (size_t)(bx + r) * NDIM + by + tx;  // Ut[bx+r, by+tx]
        g_Uthi[o] = h;
        g_Utlo[o] = __float2bfloat16(v - __bfloat162float(h));
    }
}

__global__ void prep_X_k(const float* __restrict__ X) {
    __shared__ float t[32][33];
    const int bx = blockIdx.x * 32, by = blockIdx.y * 32;   // bx over F, by over N
    const int tx = threadIdx.x, ty = threadIdx.y;
#pragma unroll
    for (int i = 0; i < 4; ++i) {
        int r = ty + i * 8;
        t[r][tx] = X[(size_t)(by + r) * FDIM + bx + tx];
    }
    __syncthreads();
#pragma unroll
    for (int i = 0; i < 4; ++i) {
        int r = ty + i * 8;
        float v = t[tx][r];                            // X[by+tx, bx+r]
        __nv_bfloat16 h = __float2bfloat16(v);
        size_t o = (size_t)(bx + r) * NDIM + by + tx;  // Xt[bx+r, by+tx]
        g_Xthi[o] = h;
        g_Xtlo[o] = __float2bfloat16(v - __bfloat162float(h));
    }
}

// --------------------------- mma.sync GEMM kernel ---------------------------
// C[m0.., n0..] = A[m,k] * B[n,k]^T over K=2048, A/B bf16 hi/lo.
// mode 0: A=Xt, B=Ut; epilogue *g[col], write Wt hi/lo.
// mode 1: A=U,  B=Wt; epilogue out = alpha*X + D.
// 8 warps: warp_m in 0..3 (16 rows each), warp_n in 0..1 (32 cols each).
__global__ __launch_bounds__(256)
void gemm_mma(int mode, const float* __restrict__ X,
              const float* __restrict__ alpha, float* __restrict__ out)
{
    extern __shared__ char smem_raw[];
    const unsigned sb = (s2u(smem_raw) + 1023u) & ~1023u;

    const int tid = threadIdx.x;
    const int wid = tid >> 5, lane = tid & 31;
    const int warp_m = wid >> 1, warp_n = wid & 1;
    const int m0 = blockIdx.x * BT, n0 = blockIdx.y * BT;

    const __nv_bfloat16 *Ah, *Al, *Bh, *Bl;
    if (mode == 0) { Ah = g_Xthi; Al = g_Xtlo; Bh = g_Uthi; Bl = g_Utlo; }
    else           { Ah = g_Uhi;  Al = g_Ulo;  Bh = g_Wthi; Bl = g_Wtlo; }

    // -------- load plan: 8 cp.async x 16B per thread per stage --------
    const __nv_bfloat16* srcs[4] = {
        Ah + (size_t)m0 * KDIM, Al + (size_t)m0 * KDIM,
        Bh + (size_t)n0 * KDIM, Bl + (size_t)n0 * KDIM };
    unsigned soff[8], goff[8];
#pragma unroll
    for (int i = 0; i < 8; ++i) {
        int arr = i >> 1;
        int l = (i & 1) * 256 + tid;       // 0..511
        int row = l >> 3, c = l & 7;
        soff[i] = arr * 8192 + swz(row * 128 + c * 16);
        goff[i] = row * KDIM + c * 8;
    }

    auto load_tile = [&](int t, int stage) {
        const unsigned st = sb + stage * STAGE_BYTES;
        const unsigned kb = t * KT;
#pragma unroll
        for (int i = 0; i < 8; ++i)
            cpa16(st + soff[i], srcs[i >> 1] + goff[i] + kb);
        asm volatile("cp.async.commit_group;" ::: "memory");
    };

    // -------- ldmatrix address bases (within-tile byte offsets) --------
    const unsigned abase =
        (warp_m * 16 + ((lane >> 3) & 1) * 8 + (lane & 7)) * 128 + (lane >> 4) * 16;
    unsigned bbase[2];
#pragma unroll
    for (int nf2 = 0; nf2 < 2; ++nf2) {
        int rowB = warp_n * 32 + nf2 * 16 + ((lane >> 4) & 1) * 8 + (lane & 7);
        bbase[nf2] = rowB * 128 + ((lane >> 3) & 1) * 16;
    }

    float accH[4][4] = {};   // Ah*Bh
    float accX[4][4] = {};   // Ah*Bl + Al*Bh  (independent chains)

    load_tile(0, 0);
    for (int t = 0; t < NKT; ++t) {
        if (t + 1 < NKT) {
            load_tile(t + 1, (t + 1) & 1);
            asm volatile("cp.async.wait_group 1;" ::: "memory");
        } else {
            asm volatile("cp.async.wait_group 0;" ::: "memory");
        }
        __syncthreads();

        const unsigned stA = sb + (t & 1) * STAGE_BYTES;
        const unsigned stB = stA + 16384;
#pragma unroll
        for (int ks = 0; ks < 4; ++ks) {
            unsigned ah[4], al[4], bh[2][4], bl[2][4];
            ldm_x4(ah, stA + swz(abase + ks * 32));
            ldm_x4(al, stA + 8192 + swz(abase + ks * 32));
#pragma unroll
            for (int nf2 = 0; nf2 < 2; ++nf2) {
                ldm_x4(bh[nf2], stB + swz(bbase[nf2] + ks * 32));
                ldm_x4(bl[nf2], stB + 8192 + swz(bbase[nf2] + ks * 32));
            }
            // wave 1: hh into accH (4 independent)
#pragma unroll
            for (int nf = 0; nf < 4; ++nf)
                mma16816(accH[nf], ah, &bh[nf >> 1][(nf & 1) * 2]);
            // wave 2: hl into accX (4 independent)
#pragma unroll
            for (int nf = 0; nf < 4; ++nf)
                mma16816(accX[nf], ah, &bl[nf >> 1][(nf & 1) * 2]);
            // wave 3: lh into accX (RAW distance 4 >= latency window)
#pragma unroll
            for (int nf = 0; nf < 4; ++nf)
                mma16816(accX[nf], al, &bh[nf >> 1][(nf & 1) * 2]);
        }
        __syncthreads();
    }

    // ------------------------------ epilogue --------------------------------
    const int rbase = m0 + warp_m * 16 + (lane >> 2);
    const int cbase0 = n0 + warp_n * 32 + (lane & 3) * 2;

    if (mode == 0) {
#pragma unroll
        for (int nf = 0; nf < 4; ++nf) {
            const int cb = cbase0 + nf * 8;
            const float g0 = g_g[cb], g1 = g_g[cb + 1];
#pragma unroll
            for (int h = 0; h < 2; ++h) {
                const int row = rbase + h * 8;
                float v0 = (accH[nf][h * 2 + 0] + accX[nf][h * 2 + 0]) * g0;
                float v1 = (accH[nf][h * 2 + 1] + accX[nf][h * 2 + 1]) * g1;
                __nv_bfloat16 h0 = __float2bfloat16(v0);
                __nv_bfloat16 h1 = __float2bfloat16(v1);
                __nv_bfloat162 hv; hv.x = h0; hv.y = h1;
                __nv_bfloat162 lv;
                lv.x = __float2bfloat16(v0 - __bfloat162float(h0));
                lv.y = __float2bfloat16(v1 - __bfloat162float(h1));
                *(__nv_bfloat162*)(g_Wthi + (size_t)row * NDIM + cb) = hv;
                *(__nv_bfloat162*)(g_Wtlo + (size_t)row * NDIM + cb) = lv;
            }
        }
    } else {
        const float av = alpha[0];
#pragma unroll
        for (int nf = 0; nf < 4; ++nf) {
            const int cb = cbase0 + nf * 8;
#pragma unroll
            for (int h = 0; h < 2; ++h) {
                const int row = rbase + h * 8;
                const float2 xv = *(const float2*)(X + (size_t)row * FDIM + cb);
                float2 o;
                o.x = av * xv.x + accH[nf][h * 2 + 0] + accX[nf][h * 2 + 0];
                o.y = av * xv.y + accH[nf][h * 2 + 1] + accX[nf][h * 2 + 1];
                *(float2*)(out + (size_t)row * FDIM + cb) = o;
            }
        }
    }
}

// ---------------------------------------------------------------------------
extern "C" void kernel_launch(void* const* d_in, const int* in_sizes, int n_in,
                              void* d_out, int out_size)
{
    const float* X     = (const float*)d_in[0];  // [N,F]
    const float* Lam   = (const float*)d_in[1];  // [N,N] diagonal
    const float* U     = (const float*)d_in[2];  // [N,N]
    const float* a     = (const float*)d_in[3];
    const float* b     = (const float*)d_in[4];
    const float* c     = (const float*)d_in[5];
    const float* alpha = (const float*)d_in[6];
    // d_in[7] = edge_index (unused by the reference math)
    const int nf = in_sizes[3];

    static bool attr_set = false;
    if (!attr_set) {
        cudaFuncSetAttribute(gemm_mma, cudaFuncAttributeMaxDynamicSharedMemorySize, SMEM_DYN);
        attr_set = true;
    }

    prep_g_k<<<NDIM / 256, 256>>>(Lam, a, b, c, nf);
    dim3 bt(32, 8);
    prep_X_k<<<dim3(FDIM / 32, NDIM / 32), bt>>>(X);
    prep_U_k<<<dim3(NDIM / 32, NDIM / 32), bt>>>(U);

    // GEMM1: M=FDIM(256) x N=NDIM(2048):  grid 4 x 32
    gemm_mma<<<dim3(FDIM / BT, NDIM / BT), 256, SMEM_DYN>>>(0, X, alpha, (float*)d_out);
    // GEMM2: M=NDIM(2048) x N=FDIM(256):  grid 32 x 4
    gemm_mma<<<dim3(NDIM / BT, FDIM / BT), 256, SMEM_DYN>>>(1, X, alpha, (float*)d_out);
}

// round 8
// speedup vs baseline: 1.1933x; 1.0661x over previous
#include <cuda_runtime.h>
#include <cuda_bf16.h>
#include <cstdint>

// ============================================================================
// out = alpha*x + U * diag(g(lam)) * U^T * x       (Lambda diagonal)
// g(l) = sum_i 4*c_i/(a_i-b_i)^2 * relu((a_i-l)(l-b_i))
//
// Engine: mma.sync m16n8k16 bf16 (fp32 accum), hi/lo compensation
// (D += Ah*Bh + Ah*Bl + Al*Bh).  R8: split-K=2 (gridDim.z) -> 256 CTAs,
// 2 co-resident CTAs/SM for latency hiding. fp32 partials to per-split
// scratch (deterministic), merged by two light kernels.
// ============================================================================

#define NDIM 2048
#define FDIM 256
#define KDIM 2048
#define KHALF (KDIM / 2)
#define BT   64            // CTA tile (M and N)
#define KT   64            // k-tile (64 bf16 = 128B row -> SW128 atoms)
#define NKT  (KHALF / KT)  // 16 per split

#define STAGE_BYTES 32768  // Ah 8K | Al 8K | Bh 8K | Bl 8K
#define SMEM_DYN    (1024 + 2 * STAGE_BYTES)

// ------------------------- device scratch (no cudaMalloc) -------------------
__device__ __align__(16) __nv_bfloat16 g_Uhi [NDIM * NDIM];
__device__ __align__(16) __nv_bfloat16 g_Ulo [NDIM * NDIM];
__device__ __align__(16) __nv_bfloat16 g_Uthi[NDIM * NDIM];
__device__ __align__(16) __nv_bfloat16 g_Utlo[NDIM * NDIM];
__device__ __align__(16) __nv_bfloat16 g_Xthi[FDIM * NDIM];
__device__ __align__(16) __nv_bfloat16 g_Xtlo[FDIM * NDIM];
__device__ __align__(16) __nv_bfloat16 g_Wthi[FDIM * NDIM];
__device__ __align__(16) __nv_bfloat16 g_Wtlo[FDIM * NDIM];
__device__ __align__(16) float g_p[2][FDIM * NDIM];   // GEMM1 split partials
__device__ __align__(16) float g_q[2][NDIM * FDIM];   // GEMM2 split partials
__device__ float g_g[NDIM];

// ------------------------------- helpers ------------------------------------
__device__ __forceinline__ unsigned s2u(const void* p) {
    unsigned a;
    asm("{ .reg .u64 t; cvta.to.shared.u64 t, %1; cvt.u32.u64 %0, t; }" : "=r"(a) : "l"(p));
    return a;
}
__device__ __forceinline__ unsigned swz(unsigned o) { return o ^ ((o >> 3) & 0x70); }

__device__ __forceinline__ void cpa16(unsigned s, const void* g) {
    asm volatile("cp.async.cg.shared.global [%0], [%1], 16;" :: "r"(s), "l"(g));
}
__device__ __forceinline__ void ldm_x4(unsigned* r, unsigned addr) {
    asm volatile("ldmatrix.sync.aligned.m8n8.x4.shared.b16 {%0,%1,%2,%3}, [%4];"
                 : "=r"(r[0]), "=r"(r[1]), "=r"(r[2]), "=r"(r[3]) : "r"(addr));
}
__device__ __forceinline__ void mma16816(float* d, const unsigned* a, const unsigned* b) {
    asm volatile("mma.sync.aligned.m16n8k16.row.col.f32.bf16.bf16.f32 "
                 "{%0,%1,%2,%3}, {%4,%5,%6,%7}, {%8,%9}, {%0,%1,%2,%3};"
                 : "+f"(d[0]), "+f"(d[1]), "+f"(d[2]), "+f"(d[3])
                 : "r"(a[0]), "r"(a[1]), "r"(a[2]), "r"(a[3]), "r"(b[0]), "r"(b[1]));
}

// ------------------------------ prep kernels --------------------------------
__global__ void prep_g_k(const float* __restrict__ lam, const float* __restrict__ a,
                         const float* __restrict__ b, const float* __restrict__ c, int nf) {
    int j = blockIdx.x * blockDim.x + threadIdx.x;
    if (j >= NDIM) return;
    float lv = lam[(size_t)j * NDIM + j];
    float g = 0.f;
    for (int i = 0; i < nf; ++i) {
        float at = a[i], bt = b[i];
        float d = (at - lv) * (lv - bt);
        d = d > 0.f ? d : 0.f;
        float ab = at - bt;
        g += (4.f * c[i] / (ab * ab)) * d;
    }
    g_g[j] = g;
}

__global__ void prep_U_k(const float* __restrict__ U) {
    __shared__ float t[32][33];
    const int bx = blockIdx.x * 32, by = blockIdx.y * 32;
    const int tx = threadIdx.x, ty = threadIdx.y;
#pragma unroll
    for (int i = 0; i < 4; ++i) {
        int r = ty + i * 8;
        float v = U[(size_t)(by + r) * NDIM + bx + tx];
        t[r][tx] = v;
        __nv_bfloat16 h = __float2bfloat16(v);
        size_t o = (size_t)(by + r) * NDIM + bx + tx;
        g_Uhi[o] = h;
        g_Ulo[o] = __float2bfloat16(v - __bfloat162float(h));
    }
    __syncthreads();
#pragma unroll
    for (int i = 0; i < 4; ++i) {
        int r = ty + i * 8;
        float v = t[tx][r];                            // U[by+tx, bx+r]
        __nv_bfloat16 h = __float2bfloat16(v);
        size_t o = (size_t)(bx + r) * NDIM + by + tx;  // Ut[bx+r, by+tx]
        g_Uthi[o] = h;
        g_Utlo[o] = __float2bfloat16(v - __bfloat162float(h));
    }
}

__global__ void prep_X_k(const float* __restrict__ X) {
    __shared__ float t[32][33];
    const int bx = blockIdx.x * 32, by = blockIdx.y * 32;   // bx over F, by over N
    const int tx = threadIdx.x, ty = threadIdx.y;
#pragma unroll
    for (int i = 0; i < 4; ++i) {
        int r = ty + i * 8;
        t[r][tx] = X[(size_t)(by + r) * FDIM + bx + tx];
    }
    __syncthreads();
#pragma unroll
    for (int i = 0; i < 4; ++i) {
        int r = ty + i * 8;
        float v = t[tx][r];                            // X[by+tx, bx+r]
        __nv_bfloat16 h = __float2bfloat16(v);
        size_t o = (size_t)(bx + r) * NDIM + by + tx;  // Xt[bx+r, by+tx]
        g_Xthi[o] = h;
        g_Xtlo[o] = __float2bfloat16(v - __bfloat162float(h));
    }
}

// ------------------------------ merge kernels -------------------------------
// merge1: Wt = g[col] * (p0 + p1)  -> bf16 hi/lo       [FDIM x NDIM]
__global__ void merge1_k() {
    int i4 = (blockIdx.x * 256 + threadIdx.x) * 4;
    int col = i4 & (NDIM - 1);
    float4 p0 = *(const float4*)(g_p[0] + i4);
    float4 p1 = *(const float4*)(g_p[1] + i4);
    float4 gg = *(const float4*)(g_g + col);
    float v0 = (p0.x + p1.x) * gg.x;
    float v1 = (p0.y + p1.y) * gg.y;
    float v2 = (p0.z + p1.z) * gg.z;
    float v3 = (p0.w + p1.w) * gg.w;
    __nv_bfloat16 h0 = __float2bfloat16(v0), h1 = __float2bfloat16(v1);
    __nv_bfloat16 h2 = __float2bfloat16(v2), h3 = __float2bfloat16(v3);
    __nv_bfloat16 hv[4] = {h0, h1, h2, h3};
    __nv_bfloat16 lv[4] = {
        __float2bfloat16(v0 - __bfloat162float(h0)),
        __float2bfloat16(v1 - __bfloat162float(h1)),
        __float2bfloat16(v2 - __bfloat162float(h2)),
        __float2bfloat16(v3 - __bfloat162float(h3)) };
    *(uint2*)(g_Wthi + i4) = *(uint2*)hv;
    *(uint2*)(g_Wtlo + i4) = *(uint2*)lv;
}

// merge2: out = alpha*X + q0 + q1                      [NDIM x FDIM]
__global__ void merge2_k(const float* __restrict__ X,
                         const float* __restrict__ alpha, float* __restrict__ out) {
    int i4 = (blockIdx.x * 256 + threadIdx.x) * 4;
    const float av = alpha[0];
    float4 q0 = *(const float4*)(g_q[0] + i4);
    float4 q1 = *(const float4*)(g_q[1] + i4);
    float4 xv = *(const float4*)(X + i4);
    float4 o;
    o.x = av * xv.x + q0.x + q1.x;
    o.y = av * xv.y + q0.y + q1.y;
    o.z = av * xv.z + q0.z + q1.z;
    o.w = av * xv.w + q0.w + q1.w;
    *(float4*)(out + i4) = o;
}

// --------------------------- mma.sync GEMM kernel ---------------------------
// Partial C = A[m, k_half] * B[n, k_half]^T, fp32 partials to scratch.
// mode 0: A=Xt, B=Ut -> g_p[z];   mode 1: A=U, B=Wt -> g_q[z].
// 8 warps: warp_m in 0..3 (16 rows), warp_n in 0..1 (32 cols).
__global__ __launch_bounds__(256)
void gemm_mma(int mode)
{
    extern __shared__ char smem_raw[];
    const unsigned sb = (s2u(smem_raw) + 1023u) & ~1023u;

    const int tid = threadIdx.x;
    const int wid = tid >> 5, lane = tid & 31;
    const int warp_m = wid >> 1, warp_n = wid & 1;
    const int m0 = blockIdx.x * BT, n0 = blockIdx.y * BT;
    const int kofs = blockIdx.z * KHALF;

    const __nv_bfloat16 *Ah, *Al, *Bh, *Bl;
    float* pout;
    int ldp;
    if (mode == 0) { Ah = g_Xthi; Al = g_Xtlo; Bh = g_Uthi; Bl = g_Utlo;
                     pout = g_p[blockIdx.z]; ldp = NDIM; }
    else           { Ah = g_Uhi;  Al = g_Ulo;  Bh = g_Wthi; Bl = g_Wtlo;
                     pout = g_q[blockIdx.z]; ldp = FDIM; }

    // -------- load plan: 8 cp.async x 16B per thread per stage --------
    const __nv_bfloat16* srcs[4] = {
        Ah + (size_t)m0 * KDIM + kofs, Al + (size_t)m0 * KDIM + kofs,
        Bh + (size_t)n0 * KDIM + kofs, Bl + (size_t)n0 * KDIM + kofs };
    unsigned soff[8], goff[8];
#pragma unroll
    for (int i = 0; i < 8; ++i) {
        int arr = i >> 1;
        int l = (i & 1) * 256 + tid;       // 0..511
        int row = l >> 3, c = l & 7;
        soff[i] = arr * 8192 + swz(row * 128 + c * 16);
        goff[i] = row * KDIM + c * 8;
    }

    auto load_tile = [&](int t, int stage) {
        const unsigned st = sb + stage * STAGE_BYTES;
        const unsigned kb = t * KT;
#pragma unroll
        for (int i = 0; i < 8; ++i)
            cpa16(st + soff[i], srcs[i >> 1] + goff[i] + kb);
        asm volatile("cp.async.commit_group;" ::: "memory");
    };

    // -------- ldmatrix address bases --------
    const unsigned abase =
        (warp_m * 16 + ((lane >> 3) & 1) * 8 + (lane & 7)) * 128 + (lane >> 4) * 16;
    unsigned bbase[2];
#pragma unroll
    for (int nf2 = 0; nf2 < 2; ++nf2) {
        int rowB = warp_n * 32 + nf2 * 16 + ((lane >> 4) & 1) * 8 + (lane & 7);
        bbase[nf2] = rowB * 128 + ((lane >> 3) & 1) * 16;
    }

    float acc[4][4] = {};

    load_tile(0, 0);
    for (int t = 0; t < NKT; ++t) {
        if (t + 1 < NKT) {
            load_tile(t + 1, (t + 1) & 1);
            asm volatile("cp.async.wait_group 1;" ::: "memory");
        } else {
            asm volatile("cp.async.wait_group 0;" ::: "memory");
        }
        __syncthreads();

        const unsigned stA = sb + (t & 1) * STAGE_BYTES;
        const unsigned stB = stA + 16384;
#pragma unroll
        for (int ks = 0; ks < 4; ++ks) {
            unsigned ah[4], al[4], bh[2][4], bl[2][4];
            ldm_x4(ah, stA + swz(abase + ks * 32));
            ldm_x4(al, stA + 8192 + swz(abase + ks * 32));
#pragma unroll
            for (int nf2 = 0; nf2 < 2; ++nf2) {
                ldm_x4(bh[nf2], stB + swz(bbase[nf2] + ks * 32));
                ldm_x4(bl[nf2], stB + 8192 + swz(bbase[nf2] + ks * 32));
            }
#pragma unroll
            for (int nf = 0; nf < 4; ++nf) {
                const unsigned* bhp = &bh[nf >> 1][(nf & 1) * 2];
                const unsigned* blp = &bl[nf >> 1][(nf & 1) * 2];
                mma16816(acc[nf], ah, bhp);
                mma16816(acc[nf], ah, blp);
                mma16816(acc[nf], al, bhp);
            }
        }
        __syncthreads();
    }

    // ---------------- epilogue: fp32 partials to scratch --------------------
    const int rbase = m0 + warp_m * 16 + (lane >> 2);
    const int cbase0 = n0 + warp_n * 32 + (lane & 3) * 2;
#pragma unroll
    for (int nf = 0; nf < 4; ++nf) {
        const int cb = cbase0 + nf * 8;
#pragma unroll
        for (int h = 0; h < 2; ++h) {
            const int row = rbase + h * 8;
            float2 v; v.x = acc[nf][h * 2 + 0]; v.y = acc[nf][h * 2 + 1];
            *(float2*)(pout + (size_t)row * ldp + cb) = v;
        }
    }
}

// ---------------------------------------------------------------------------
extern "C" void kernel_launch(void* const* d_in, const int* in_sizes, int n_in,
                              void* d_out, int out_size)
{
    const float* X     = (const float*)d_in[0];  // [N,F]
    const float* Lam   = (const float*)d_in[1];  // [N,N] diagonal
    const float* U     = (const float*)d_in[2];  // [N,N]
    const float* a     = (const float*)d_in[3];
    const float* b     = (const float*)d_in[4];
    const float* c     = (const float*)d_in[5];
    const float* alpha = (const float*)d_in[6];
    // d_in[7] = edge_index (unused by the reference math)
    const int nf = in_sizes[3];

    static bool attr_set = false;
    if (!attr_set) {
        cudaFuncSetAttribute(gemm_mma, cudaFuncAttributeMaxDynamicSharedMemorySize, SMEM_DYN);
        attr_set = true;
    }

    prep_g_k<<<NDIM / 256, 256>>>(Lam, a, b, c, nf);
    dim3 bt(32, 8);
    prep_X_k<<<dim3(FDIM / 32, NDIM / 32), bt>>>(X);
    prep_U_k<<<dim3(NDIM / 32, NDIM / 32), bt>>>(U);

    // GEMM1: M=FDIM x N=NDIM, split-K=2:  grid 4 x 32 x 2 = 256 CTAs
    gemm_mma<<<dim3(FDIM / BT, NDIM / BT, 2), 256, SMEM_DYN>>>(0);
    merge1_k<<<(FDIM * NDIM / 4) / 256, 256>>>();
    // GEMM2: M=NDIM x N=FDIM, split-K=2:  grid 32 x 4 x 2 = 256 CTAs
    gemm_mma<<<dim3(NDIM / BT, FDIM / BT, 2), 256, SMEM_DYN>>>(1);
    merge2_k<<<(NDIM * FDIM / 4) / 256, 256>>>(X, alpha, (float*)d_out);
}